// round 9
// baseline (speedup 1.0000x reference)
#include <cuda_runtime.h>
#include <math.h>

typedef unsigned long long u64;

#define HEADS 16
#define KVH 8
#define HD 128
#define HDIM 2048
#define GROUPS (HEADS/KVH)
#define MAXB 2
#define MAXS 2048
#define MAXM (MAXB*MAXS)

#define NW_BIG   ((long)HDIM*HDIM)
#define NW_SMALL ((long)KVH*HD*HDIM)
#define STATS_BLOCKS 512

// ---------------- device scratch (no allocations allowed) ----------------
__device__ float g_ps[4][STATS_BLOCKS];
__device__ float g_pa[4][STATS_BLOCKS];
__device__ float g_wscale[4];

__device__ __align__(16) signed char g_sgn0[HDIM*HDIM];
__device__ __align__(16) signed char g_sgn1[KVH*HD*HDIM];
__device__ __align__(16) signed char g_sgn2[KVH*HD*HDIM];
__device__ __align__(16) signed char g_sgn3[HDIM*HDIM];
__device__ __align__(16) signed char g_aq[4][(size_t)MAXM*HDIM];
__device__ float g_as[4][MAXM];
__device__ float g_qb[(size_t)MAXB*HEADS*MAXS*HD];
__device__ float g_kb[(size_t)MAXB*KVH*MAXS*HD];
__device__ float g_vb[(size_t)MAXB*KVH*MAXS*HD];
__device__ float g_ao[(size_t)MAXM*HDIM];

__device__ __forceinline__ signed char* sgn_ptr(int s){
    return (s==0)?g_sgn0:(s==1)?g_sgn1:(s==2)?g_sgn2:g_sgn3;
}

// ---------------- packed fp32x2 helpers ----------------
__device__ __forceinline__ u64 ld2(const float* p){
    return *reinterpret_cast<const u64*>(p);
}
__device__ __forceinline__ u64 fma2(u64 a, u64 b, u64 c){
    u64 d;
    asm("fma.rn.f32x2 %0, %1, %2, %3;" : "=l"(d) : "l"(a), "l"(b), "l"(c));
    return d;
}
__device__ __forceinline__ float lo2(u64 v){
    float a; asm("{ .reg .b32 hi; mov.b64 {%0, hi}, %1; }" : "=f"(a) : "l"(v)); return a;
}
__device__ __forceinline__ float hi2(u64 v){
    float a; asm("{ .reg .b32 lo; mov.b64 {lo, %0}, %1; }" : "=f"(a) : "l"(v)); return a;
}

// ---------------- weight statistics ----------------
__global__ void wstats_all_kernel(const float* __restrict__ wq, const float* __restrict__ wk,
                                  const float* __restrict__ wv, const float* __restrict__ wo){
    int slot = blockIdx.y;
    const float* W = (slot==0)?wq:(slot==1)?wk:(slot==2)?wv:wo;
    long n = (slot==0 || slot==3)? NW_BIG : NW_SMALL;
    float s=0.f, a=0.f;
    long stride = (long)gridDim.x*blockDim.x;
    for (long i = blockIdx.x*(long)blockDim.x + threadIdx.x; i<n; i+=stride){
        float w = W[i]; s += w; a += fabsf(w);
    }
    __shared__ float rs[256], ra[256];
    rs[threadIdx.x]=s; ra[threadIdx.x]=a; __syncthreads();
    for (int o=128;o>0;o>>=1){
        if ((int)threadIdx.x<o){ rs[threadIdx.x]+=rs[threadIdx.x+o]; ra[threadIdx.x]+=ra[threadIdx.x+o]; }
        __syncthreads();
    }
    if (threadIdx.x==0){
        g_ps[slot][blockIdx.x]=rs[0];
        g_pa[slot][blockIdx.x]=ra[0];
    }
}

__global__ void wsign_all_kernel(const float* __restrict__ wq, const float* __restrict__ wk,
                                 const float* __restrict__ wv, const float* __restrict__ wo){
    int slot = blockIdx.y;
    const float* W = (slot==0)?wq:(slot==1)?wk:(slot==2)?wv:wo;
    long n = (slot==0 || slot==3)? NW_BIG : NW_SMALL;
    __shared__ float rs[256], ra[256];
    {
        float s = g_ps[slot][threadIdx.x] + g_ps[slot][threadIdx.x+256];
        float a = g_pa[slot][threadIdx.x] + g_pa[slot][threadIdx.x+256];
        rs[threadIdx.x]=s; ra[threadIdx.x]=a; __syncthreads();
        for (int o=128;o>0;o>>=1){
            if ((int)threadIdx.x<o){ rs[threadIdx.x]+=rs[threadIdx.x+o]; ra[threadIdx.x]+=ra[threadIdx.x+o]; }
            __syncthreads();
        }
    }
    float e  = rs[0]/(float)n;
    float sc = fmaxf(ra[0]/(float)n, 1e-8f);
    if (blockIdx.x==0 && threadIdx.x==0) g_wscale[slot]=sc;
    signed char* S8 = sgn_ptr(slot);
    long stride = (long)gridDim.x*blockDim.x;
    for (long i = blockIdx.x*(long)blockDim.x + threadIdx.x; i<n; i+=stride){
        float d = W[i]-e;
        S8[i] = (d>0.f)?(signed char)1:((d<0.f)?(signed char)-1:(signed char)0);
    }
}

// ---------------- rmsnorm + activation quant ----------------
__global__ void act_quant3_kernel(const float* __restrict__ X,
                                  const float* __restrict__ nq,
                                  const float* __restrict__ nk,
                                  const float* __restrict__ nv){
    int m = blockIdx.x, tid = threadIdx.x;
    const float* x = X + (size_t)m*HDIM;
    float v[8]; float ss=0.f;
    #pragma unroll
    for (int i=0;i<8;i++){
        float f = x[tid + i*256];
        f = fminf(fmaxf(f,-100.f),100.f);
        v[i]=f; ss += f*f;
    }
    __shared__ float red[256];
    red[tid]=ss; __syncthreads();
    for (int o=128;o>0;o>>=1){ if (tid<o) red[tid]+=red[tid+o]; __syncthreads(); }
    float var = red[0]*(1.f/(float)HDIM);
    var = fmaxf(var, 1e-5f);
    float rs = 1.f/sqrtf(var + 1e-5f);
    __syncthreads();
    #pragma unroll
    for (int i=0;i<8;i++){
        float b = v[i]*rs;
        v[i] = fminf(fmaxf(b,-10.f),10.f);
    }
    const float* nws[3] = {nq, nk, nv};
    #pragma unroll 1
    for (int slot=0; slot<3; slot++){
        const float* nw = nws[slot];
        float w[8]; float mx=0.f;
        #pragma unroll
        for (int i=0;i<8;i++){
            float t = v[i]*nw[tid+i*256];
            t = fminf(fmaxf(t,-50.f),50.f);
            w[i]=t; mx = fmaxf(mx, fabsf(t));
        }
        red[tid]=mx; __syncthreads();
        for (int o=128;o>0;o>>=1){ if (tid<o) red[tid]=fmaxf(red[tid],red[tid+o]); __syncthreads(); }
        float maxv = fmaxf(red[0], 1e-4f);
        __syncthreads();
        float scale = 127.f/maxv;
        signed char* out8 = g_aq[slot] + (size_t)m*HDIM;
        #pragma unroll
        for (int i=0;i<8;i++){
            int q = __float2int_rn(w[i]*scale);
            q = max(-128, min(127, q));
            out8[tid+i*256] = (signed char)q;
        }
        if (tid==0) g_as[slot][m] = maxv*(1.f/127.f);
    }
}

__global__ void act_quant_kernel(const float* __restrict__ nw, int slot){
    const float* X = g_ao;
    int m = blockIdx.x, tid = threadIdx.x;
    const float* x = X + (size_t)m*HDIM;
    float v[8]; float ss=0.f;
    #pragma unroll
    for (int i=0;i<8;i++){
        float f = x[tid + i*256];
        f = fminf(fmaxf(f,-100.f),100.f);
        v[i]=f; ss += f*f;
    }
    __shared__ float red[256];
    red[tid]=ss; __syncthreads();
    for (int o=128;o>0;o>>=1){ if (tid<o) red[tid]+=red[tid+o]; __syncthreads(); }
    float var = red[0]*(1.f/(float)HDIM);
    var = fmaxf(var, 1e-5f);
    float rs = 1.f/sqrtf(var + 1e-5f);
    __syncthreads();
    float mx=0.f;
    #pragma unroll
    for (int i=0;i<8;i++){
        float b = v[i]*rs;
        b = fminf(fmaxf(b,-10.f),10.f);
        float w = b*nw[tid+i*256];
        w = fminf(fmaxf(w,-50.f),50.f);
        v[i]=w; mx = fmaxf(mx, fabsf(w));
    }
    red[tid]=mx; __syncthreads();
    for (int o=128;o>0;o>>=1){ if (tid<o) red[tid]=fmaxf(red[tid],red[tid+o]); __syncthreads(); }
    float maxv = fmaxf(red[0], 1e-4f);
    float scale = 127.f/maxv;
    signed char* out8 = g_aq[slot] + (size_t)m*HDIM;
    #pragma unroll
    for (int i=0;i<8;i++){
        int q = __float2int_rn(v[i]*scale);
        q = max(-128, min(127, q));
        out8[tid+i*256] = (signed char)q;
    }
    if (tid==0) g_as[slot][m] = maxv*(1.f/127.f);
}

// ---------------- int8 x ternary GEMM via mma.sync (IMMA tensor cores) ----------------
__device__ __forceinline__ void mma_s8(int* c, const int* a, const int* b){
    asm volatile(
        "mma.sync.aligned.m16n8k32.row.col.s32.s8.s8.s32 "
        "{%0,%1,%2,%3}, {%4,%5,%6,%7}, {%8,%9}, {%0,%1,%2,%3};\n"
        : "+r"(c[0]), "+r"(c[1]), "+r"(c[2]), "+r"(c[3])
        : "r"(a[0]), "r"(a[1]), "r"(a[2]), "r"(a[3]), "r"(b[0]), "r"(b[1]));
}

__device__ __forceinline__ void gemm_body(int slot, int N, int S, float* __restrict__ Cext,
                                          int m0, int n0){
    __shared__ int As_s[128*32];
    __shared__ int Bs_s[64*32];
    const int KI4 = HDIM/16;
    int tid = threadIdx.x;
    const int4* A4 = (const int4*)(g_aq[slot]);
    const int4* B4 = (const int4*)sgn_ptr(slot);

    int warp = tid>>5, lane = tid&31;
    int wm = warp&3, wn = warp>>2;
    int q = lane>>2, t = lane&3;

    int acc[2][4][4];
    #pragma unroll
    for (int mi=0;mi<2;mi++)
        #pragma unroll
        for (int ni=0;ni<4;ni++)
            #pragma unroll
            for (int e=0;e<4;e++) acc[mi][ni][e]=0;

    for (int k0=0; k0<HDIM; k0+=128){
        int kb = k0>>4;
        #pragma unroll
        for (int i=0;i<4;i++){
            int idx = tid + i*256;
            int r = idx>>3, b = idx&7;
            int4 val = A4[(size_t)(m0+r)*KI4 + kb + b];
            ((int4*)As_s)[r*8 + (b ^ (r&7))] = val;
        }
        #pragma unroll
        for (int i=0;i<2;i++){
            int idx = tid + i*256;
            int r = idx>>3, b = idx&7;
            int4 val = B4[(size_t)(n0+r)*KI4 + kb + b];
            ((int4*)Bs_s)[r*8 + (b ^ (r&7))] = val;
        }
        __syncthreads();
        #pragma unroll
        for (int s=0;s<4;s++){
            int a[2][4], bf[4][2];
            #pragma unroll
            for (int mi=0;mi<2;mi++){
                int r0 = wm*32 + mi*16 + q;
                int r1 = r0 + 8;
                a[mi][0] = As_s[r0*32 + ((2*s+0)^(r0&7))*4 + t];
                a[mi][1] = As_s[r1*32 + ((2*s+0)^(r1&7))*4 + t];
                a[mi][2] = As_s[r0*32 + ((2*s+1)^(r0&7))*4 + t];
                a[mi][3] = As_s[r1*32 + ((2*s+1)^(r1&7))*4 + t];
            }
            #pragma unroll
            for (int ni=0;ni<4;ni++){
                int rn = wn*32 + ni*8 + q;
                bf[ni][0] = Bs_s[rn*32 + ((2*s+0)^(rn&7))*4 + t];
                bf[ni][1] = Bs_s[rn*32 + ((2*s+1)^(rn&7))*4 + t];
            }
            #pragma unroll
            for (int mi=0;mi<2;mi++)
                #pragma unroll
                for (int ni=0;ni<4;ni++)
                    mma_s8(acc[mi][ni], a[mi], bf[ni]);
        }
        __syncthreads();
    }

    float ws = g_wscale[slot];
    float* Cq = (slot==0)? g_qb : (slot==1)? g_kb : g_vb;
    int NH = N>>7;
    #pragma unroll
    for (int mi=0;mi<2;mi++){
        #pragma unroll
        for (int h=0;h<2;h++){
            int m = m0 + wm*32 + mi*16 + q + 8*h;
            float fsc = g_as[slot][m]*ws;
            int b_ = m/S, sdx = m - b_*S;
            #pragma unroll
            for (int ni=0;ni<4;ni++){
                #pragma unroll
                for (int e=0;e<2;e++){
                    int n = n0 + wn*32 + ni*8 + t*2 + e;
                    float val = (float)acc[mi][ni][2*h+e]*fsc;
                    if (slot==3){
                        Cext[(size_t)m*N + n] = val;
                    } else {
                        int hh = n>>7, d = n&127;
                        Cq[(((size_t)(b_*NH+hh))*S + sdx)*HD + d] = val;
                    }
                }
            }
        }
    }
}

__global__ void __launch_bounds__(256) imma_qkv_kernel(int S){
    int slot = blockIdx.z;
    int N = (slot==0)? HDIM : KVH*HD;
    if (slot>0 && (int)blockIdx.x >= N/64) return;
    gemm_body(slot, N, S, nullptr, blockIdx.y*128, blockIdx.x*64);
}

__global__ void __launch_bounds__(256) imma_o_kernel(int S, float* __restrict__ Cext){
    gemm_body(3, HDIM, S, Cext, blockIdx.y*128, blockIdx.x*64);
}

// ---------------- RoPE (q and k fused, in-place) ----------------
__global__ void rope_all_kernel(int S, long tq, long total){
    long idx = blockIdx.x*(long)blockDim.x + threadIdx.x;
    if (idx>=total) return;
    float* buf; long lidx;
    if (idx < tq){ buf = g_qb; lidx = idx; }
    else         { buf = g_kb; lidx = idx - tq; }
    int i = (int)(lidx & 63);
    long row = lidx >> 6;
    int s = (int)(row % S);
    size_t base = (size_t)row*HD;
    float inv = powf(10000.f, -((float)i)*(1.f/64.f));
    float fr = (float)s * inv;
    float sn, cs; sincosf(fr,&sn,&cs);
    float x1 = buf[base+i], x2 = buf[base+i+64];
    buf[base+i]    = x1*cs - x2*sn;
    buf[base+i+64] = x2*cs + x1*sn;
}

// ---------------- flash attention v2: Q128 x K128, 512 threads, occ 1 ----------------
// Thread tile: 4 rows x 8 cols (QK) and 4 rows x 8 dims (PV), f32x2 packed over
// the reduction axis in BOTH phases (V stored transposed in smem for PV).
// Lane mapping: warp w -> rows w*8 + (lane>>4)*4 .. +3 ; cols/dims (lane&15)+16j.
// All LDS are 16-address broadcast patterns at pitch 130 -> conflict-free.
#define FP 130   // smem pitch (floats)
__global__ void __launch_bounds__(512,1) flash_kernel(const float* __restrict__ mask, int S){
    extern __shared__ float sh[];
    float* Qs = sh;                 // 128*130
    float* Ks = Qs + 128*FP;        // 128*130 (K row-major, then reused as V^T)
    float* Ss = Ks + 128*FP;        // 128*130 (P)
    int tid = threadIdx.x;
    int w = tid>>5, lane = tid&31;
    int hw = lane>>4, c16 = lane&15;
    int R0 = w*8 + hw*4;
    int tqi = blockIdx.x, bh = blockIdx.y;
    int b = bh/HEADS, h = bh%HEADS, hk = h/GROUPS;
    int sq0 = tqi*128;
    const float* Qg = g_qb + (((size_t)bh)*S + sq0)*HD;
    const float* Kg = g_kb + ((size_t)(b*KVH+hk)*S)*HD;
    const float* Vg = g_vb + ((size_t)(b*KVH+hk)*S)*HD;

    // Q fill (float2, row-major, pitch 130)
    for (int e=tid; e<128*64; e+=512){
        int r = e>>6, c = e&63;
        *(u64*)&Qs[r*FP + 2*c] = *(const u64*)&Qg[r*HD + 2*c];
    }

    float o4[4][8];
    #pragma unroll
    for (int i=0;i<4;i++)
        #pragma unroll
        for (int j=0;j<8;j++) o4[i][j]=0.f;
    float mreg[4], lreg[4];
    #pragma unroll
    for (int i=0;i<4;i++){ mreg[i] = __int_as_float(0xff800000); lreg[i]=0.f; }
    const float sc = 0.08838834764831845f;   // 1/sqrt(128)
    __syncthreads();

    int NT = S/128;
    for (int kt=0; kt<NT; kt++){
        // K fill (row-major)
        const float* Kt = Kg + (size_t)kt*128*HD;
        for (int e=tid; e<128*64; e+=512){
            int r = e>>6, c = e&63;
            *(u64*)&Ks[r*FP + 2*c] = *(const u64*)&Kt[r*HD + 2*c];
        }
        __syncthreads();

        // ---- QK^T: f32x2 over k ----
        {
            u64 acc[4][8];
            #pragma unroll
            for (int i=0;i<4;i++)
                #pragma unroll
                for (int j=0;j<8;j++) acc[i][j]=0ull;
            #pragma unroll 4
            for (int k2=0;k2<64;k2++){
                u64 qa[4], kb[8];
                #pragma unroll
                for (int i=0;i<4;i++) qa[i] = ld2(&Qs[(R0+i)*FP + 2*k2]);
                #pragma unroll
                for (int j=0;j<8;j++) kb[j] = ld2(&Ks[(c16+16*j)*FP + 2*k2]);
                #pragma unroll
                for (int i=0;i<4;i++)
                    #pragma unroll
                    for (int j=0;j<8;j++)
                        acc[i][j] = fma2(qa[i], kb[j], acc[i][j]);
            }

            // ---- softmax (online) ----
            #pragma unroll
            for (int i=0;i<4;i++){
                const float* mrow = mask + (size_t)(sq0+R0+i)*S + (size_t)kt*128;
                float s8[8];
                #pragma unroll
                for (int j=0;j<8;j++)
                    s8[j] = (lo2(acc[i][j]) + hi2(acc[i][j]))*sc + mrow[c16+16*j];
                float mx = s8[0];
                #pragma unroll
                for (int j=1;j<8;j++) mx = fmaxf(mx, s8[j]);
                mx = fmaxf(mx,__shfl_xor_sync(0xffffffffu,mx,1,16));
                mx = fmaxf(mx,__shfl_xor_sync(0xffffffffu,mx,2,16));
                mx = fmaxf(mx,__shfl_xor_sync(0xffffffffu,mx,4,16));
                mx = fmaxf(mx,__shfl_xor_sync(0xffffffffu,mx,8,16));
                float mn = fmaxf(mreg[i], mx);
                float su=0.f;
                #pragma unroll
                for (int j=0;j<8;j++){ float p = __expf(s8[j]-mn); s8[j]=p; su+=p; }
                su += __shfl_xor_sync(0xffffffffu,su,1,16);
                su += __shfl_xor_sync(0xffffffffu,su,2,16);
                su += __shfl_xor_sync(0xffffffffu,su,4,16);
                su += __shfl_xor_sync(0xffffffffu,su,8,16);
                float f = __expf(mreg[i]-mn);
                lreg[i] = lreg[i]*f + su;
                mreg[i] = mn;
                // stash fac in s8 path: reuse mreg trick — keep in acc slot 0? store below
                #pragma unroll
                for (int j=0;j<8;j++) Ss[(R0+i)*FP + c16+16*j] = s8[j];
                // fold old o by f now (32 mults, avoids extra fac storage)
                #pragma unroll
                for (int j=0;j<8;j++) o4[i][j] *= f;
            }
        }
        __syncthreads();

        // V fill TRANSPOSED into Ks: Vt[d][kk] = V[kk][d]
        {
            const float* Vt = Vg + (size_t)kt*128*HD;
            for (int e=tid; e<128*128; e+=512){
                int kk = e>>7, d = e&127;
                Ks[d*FP + kk] = Vt[e];
            }
        }
        __syncthreads();

        // ---- P @ V: f32x2 over kk (both operands contiguous, no packs) ----
        {
            u64 pacc[4][8];
            #pragma unroll
            for (int i=0;i<4;i++)
                #pragma unroll
                for (int j=0;j<8;j++) pacc[i][j]=0ull;
            #pragma unroll 4
            for (int k2=0;k2<64;k2++){
                u64 pp[4], vv[8];
                #pragma unroll
                for (int i=0;i<4;i++) pp[i] = ld2(&Ss[(R0+i)*FP + 2*k2]);
                #pragma unroll
                for (int j=0;j<8;j++) vv[j] = ld2(&Ks[(c16+16*j)*FP + 2*k2]);
                #pragma unroll
                for (int i=0;i<4;i++)
                    #pragma unroll
                    for (int j=0;j<8;j++)
                        pacc[i][j] = fma2(pp[i], vv[j], pacc[i][j]);
            }
            #pragma unroll
            for (int i=0;i<4;i++)
                #pragma unroll
                for (int j=0;j<8;j++)
                    o4[i][j] += lo2(pacc[i][j]) + hi2(pacc[i][j]);
        }
        __syncthreads();
    }

    #pragma unroll
    for (int i=0;i<4;i++){
        float inv = 1.f/lreg[i];
        size_t rowbase = ((size_t)b*S + (size_t)(sq0+R0+i))*HDIM + (size_t)h*HD;
        #pragma unroll
        for (int j=0;j<8;j++)
            g_ao[rowbase + c16+16*j] = o4[i][j]*inv;
    }
}

// ---------------- launch ----------------
extern "C" void kernel_launch(void* const* d_in, const int* in_sizes, int n_in,
                              void* d_out, int out_size){
    const float* hidden = (const float*)d_in[0];
    const float* mask   = (const float*)d_in[1];
    const float* wq     = (const float*)d_in[2];
    const float* wk     = (const float*)d_in[3];
    const float* wv     = (const float*)d_in[4];
    const float* wo     = (const float*)d_in[5];
    const float* nq     = (const float*)d_in[6];
    const float* nk     = (const float*)d_in[7];
    const float* nv     = (const float*)d_in[8];
    const float* no_    = (const float*)d_in[9];
    float* out = (float*)d_out;

    int S = MAXS;
    {
        long ms = in_sizes[1];
        int s = (int)(sqrt((double)ms)+0.5);
        if ((long)s*s == ms) S = s;
    }
    int M = in_sizes[0]/HDIM;   // B*S rows
    int B = M/S;

    wstats_all_kernel<<<dim3(STATS_BLOCKS,4),256>>>(wq,wk,wv,wo);          // 1
    wsign_all_kernel<<<dim3(1024,4),256>>>(wq,wk,wv,wo);                    // 2
    act_quant3_kernel<<<M,256>>>(hidden, nq, nk, nv);                       // 3
    imma_qkv_kernel<<<dim3(HDIM/64, M/128, 3),256>>>(S);                    // 4

    long tq = (long)B*HEADS*S*64;
    long tk = (long)B*KVH*S*64;
    rope_all_kernel<<<(unsigned)((tq+tk+255)/256),256>>>(S, tq, tq+tk);     // 5

    const int FLASH_SMEM = 128*FP*3*4;  // 199680 bytes
    cudaFuncSetAttribute(flash_kernel, cudaFuncAttributeMaxDynamicSharedMemorySize, FLASH_SMEM);
    flash_kernel<<<dim3(S/128, B*HEADS),512,FLASH_SMEM>>>(mask, S);         // 6

    act_quant_kernel<<<M,256>>>(no_, 3);                                    // 7
    imma_o_kernel<<<dim3(HDIM/64, M/128),256>>>(S, out);                    // 8
}

// round 10
// speedup vs baseline: 1.0991x; 1.0991x over previous
#include <cuda_runtime.h>
#include <math.h>

typedef unsigned long long u64;

#define HEADS 16
#define KVH 8
#define HD 128
#define HDIM 2048
#define GROUPS (HEADS/KVH)
#define MAXB 2
#define MAXS 2048
#define MAXM (MAXB*MAXS)

#define NW_BIG   ((long)HDIM*HDIM)
#define NW_SMALL ((long)KVH*HD*HDIM)
#define STATS_BLOCKS 512

// ---------------- device scratch (no allocations allowed) ----------------
__device__ float g_ps[4][STATS_BLOCKS];
__device__ float g_pa[4][STATS_BLOCKS];
__device__ float g_wscale[4];

__device__ __align__(16) signed char g_sgn0[HDIM*HDIM];
__device__ __align__(16) signed char g_sgn1[KVH*HD*HDIM];
__device__ __align__(16) signed char g_sgn2[KVH*HD*HDIM];
__device__ __align__(16) signed char g_sgn3[HDIM*HDIM];
__device__ __align__(16) signed char g_aq[4][(size_t)MAXM*HDIM];
__device__ float g_as[4][MAXM];
__device__ float g_qb[(size_t)MAXB*HEADS*MAXS*HD];
__device__ float g_kb[(size_t)MAXB*KVH*MAXS*HD];
__device__ float g_vb[(size_t)MAXB*KVH*MAXS*HD];
__device__ float g_ao[(size_t)MAXM*HDIM];

__device__ __forceinline__ signed char* sgn_ptr(int s){
    return (s==0)?g_sgn0:(s==1)?g_sgn1:(s==2)?g_sgn2:g_sgn3;
}

// ---------------- packed fp32x2 helpers ----------------
__device__ __forceinline__ u64 ld2(const float* p){
    return *reinterpret_cast<const u64*>(p);
}
__device__ __forceinline__ u64 fma2(u64 a, u64 b, u64 c){
    u64 d;
    asm("fma.rn.f32x2 %0, %1, %2, %3;" : "=l"(d) : "l"(a), "l"(b), "l"(c));
    return d;
}
__device__ __forceinline__ u64 pack2f(float lo, float hi){
    u64 r;
    asm("mov.b64 %0, {%1, %2};" : "=l"(r) : "f"(lo), "f"(hi));
    return r;
}
__device__ __forceinline__ float lo2(u64 v){
    float a; asm("{ .reg .b32 hi; mov.b64 {%0, hi}, %1; }" : "=f"(a) : "l"(v)); return a;
}
__device__ __forceinline__ float hi2(u64 v){
    float a; asm("{ .reg .b32 lo; mov.b64 {lo, %0}, %1; }" : "=f"(a) : "l"(v)); return a;
}

// ---------------- weight statistics ----------------
__global__ void wstats_all_kernel(const float* __restrict__ wq, const float* __restrict__ wk,
                                  const float* __restrict__ wv, const float* __restrict__ wo){
    int slot = blockIdx.y;
    const float* W = (slot==0)?wq:(slot==1)?wk:(slot==2)?wv:wo;
    long n = (slot==0 || slot==3)? NW_BIG : NW_SMALL;
    float s=0.f, a=0.f;
    long stride = (long)gridDim.x*blockDim.x;
    for (long i = blockIdx.x*(long)blockDim.x + threadIdx.x; i<n; i+=stride){
        float w = W[i]; s += w; a += fabsf(w);
    }
    __shared__ float rs[256], ra[256];
    rs[threadIdx.x]=s; ra[threadIdx.x]=a; __syncthreads();
    for (int o=128;o>0;o>>=1){
        if ((int)threadIdx.x<o){ rs[threadIdx.x]+=rs[threadIdx.x+o]; ra[threadIdx.x]+=ra[threadIdx.x+o]; }
        __syncthreads();
    }
    if (threadIdx.x==0){
        g_ps[slot][blockIdx.x]=rs[0];
        g_pa[slot][blockIdx.x]=ra[0];
    }
}

__global__ void wsign_all_kernel(const float* __restrict__ wq, const float* __restrict__ wk,
                                 const float* __restrict__ wv, const float* __restrict__ wo){
    int slot = blockIdx.y;
    const float* W = (slot==0)?wq:(slot==1)?wk:(slot==2)?wv:wo;
    long n = (slot==0 || slot==3)? NW_BIG : NW_SMALL;
    __shared__ float rs[256], ra[256];
    {
        float s = g_ps[slot][threadIdx.x] + g_ps[slot][threadIdx.x+256];
        float a = g_pa[slot][threadIdx.x] + g_pa[slot][threadIdx.x+256];
        rs[threadIdx.x]=s; ra[threadIdx.x]=a; __syncthreads();
        for (int o=128;o>0;o>>=1){
            if ((int)threadIdx.x<o){ rs[threadIdx.x]+=rs[threadIdx.x+o]; ra[threadIdx.x]+=ra[threadIdx.x+o]; }
            __syncthreads();
        }
    }
    float e  = rs[0]/(float)n;
    float sc = fmaxf(ra[0]/(float)n, 1e-8f);
    if (blockIdx.x==0 && threadIdx.x==0) g_wscale[slot]=sc;
    signed char* S8 = sgn_ptr(slot);
    long stride = (long)gridDim.x*blockDim.x;
    for (long i = blockIdx.x*(long)blockDim.x + threadIdx.x; i<n; i+=stride){
        float d = W[i]-e;
        S8[i] = (d>0.f)?(signed char)1:((d<0.f)?(signed char)-1:(signed char)0);
    }
}

// ---------------- rmsnorm + activation quant ----------------
__global__ void act_quant3_kernel(const float* __restrict__ X,
                                  const float* __restrict__ nq,
                                  const float* __restrict__ nk,
                                  const float* __restrict__ nv){
    int m = blockIdx.x, tid = threadIdx.x;
    const float* x = X + (size_t)m*HDIM;
    float v[8]; float ss=0.f;
    #pragma unroll
    for (int i=0;i<8;i++){
        float f = x[tid + i*256];
        f = fminf(fmaxf(f,-100.f),100.f);
        v[i]=f; ss += f*f;
    }
    __shared__ float red[256];
    red[tid]=ss; __syncthreads();
    for (int o=128;o>0;o>>=1){ if (tid<o) red[tid]+=red[tid+o]; __syncthreads(); }
    float var = red[0]*(1.f/(float)HDIM);
    var = fmaxf(var, 1e-5f);
    float rs = 1.f/sqrtf(var + 1e-5f);
    __syncthreads();
    #pragma unroll
    for (int i=0;i<8;i++){
        float b = v[i]*rs;
        v[i] = fminf(fmaxf(b,-10.f),10.f);
    }
    const float* nws[3] = {nq, nk, nv};
    #pragma unroll 1
    for (int slot=0; slot<3; slot++){
        const float* nw = nws[slot];
        float w[8]; float mx=0.f;
        #pragma unroll
        for (int i=0;i<8;i++){
            float t = v[i]*nw[tid+i*256];
            t = fminf(fmaxf(t,-50.f),50.f);
            w[i]=t; mx = fmaxf(mx, fabsf(t));
        }
        red[tid]=mx; __syncthreads();
        for (int o=128;o>0;o>>=1){ if (tid<o) red[tid]=fmaxf(red[tid],red[tid+o]); __syncthreads(); }
        float maxv = fmaxf(red[0], 1e-4f);
        __syncthreads();
        float scale = 127.f/maxv;
        signed char* out8 = g_aq[slot] + (size_t)m*HDIM;
        #pragma unroll
        for (int i=0;i<8;i++){
            int q = __float2int_rn(w[i]*scale);
            q = max(-128, min(127, q));
            out8[tid+i*256] = (signed char)q;
        }
        if (tid==0) g_as[slot][m] = maxv*(1.f/127.f);
    }
}

__global__ void act_quant_kernel(const float* __restrict__ nw, int slot){
    const float* X = g_ao;
    int m = blockIdx.x, tid = threadIdx.x;
    const float* x = X + (size_t)m*HDIM;
    float v[8]; float ss=0.f;
    #pragma unroll
    for (int i=0;i<8;i++){
        float f = x[tid + i*256];
        f = fminf(fmaxf(f,-100.f),100.f);
        v[i]=f; ss += f*f;
    }
    __shared__ float red[256];
    red[tid]=ss; __syncthreads();
    for (int o=128;o>0;o>>=1){ if (tid<o) red[tid]+=red[tid+o]; __syncthreads(); }
    float var = red[0]*(1.f/(float)HDIM);
    var = fmaxf(var, 1e-5f);
    float rs = 1.f/sqrtf(var + 1e-5f);
    __syncthreads();
    float mx=0.f;
    #pragma unroll
    for (int i=0;i<8;i++){
        float b = v[i]*rs;
        b = fminf(fmaxf(b,-10.f),10.f);
        float w = b*nw[tid+i*256];
        w = fminf(fmaxf(w,-50.f),50.f);
        v[i]=w; mx = fmaxf(mx, fabsf(w));
    }
    red[tid]=mx; __syncthreads();
    for (int o=128;o>0;o>>=1){ if (tid<o) red[tid]=fmaxf(red[tid],red[tid+o]); __syncthreads(); }
    float maxv = fmaxf(red[0], 1e-4f);
    float scale = 127.f/maxv;
    signed char* out8 = g_aq[slot] + (size_t)m*HDIM;
    #pragma unroll
    for (int i=0;i<8;i++){
        int q = __float2int_rn(v[i]*scale);
        q = max(-128, min(127, q));
        out8[tid+i*256] = (signed char)q;
    }
    if (tid==0) g_as[slot][m] = maxv*(1.f/127.f);
}

// ---------------- int8 x ternary GEMM via mma.sync (IMMA tensor cores) ----------------
__device__ __forceinline__ void mma_s8(int* c, const int* a, const int* b){
    asm volatile(
        "mma.sync.aligned.m16n8k32.row.col.s32.s8.s8.s32 "
        "{%0,%1,%2,%3}, {%4,%5,%6,%7}, {%8,%9}, {%0,%1,%2,%3};\n"
        : "+r"(c[0]), "+r"(c[1]), "+r"(c[2]), "+r"(c[3])
        : "r"(a[0]), "r"(a[1]), "r"(a[2]), "r"(a[3]), "r"(b[0]), "r"(b[1]));
}

__device__ __forceinline__ void gemm_body(int slot, int N, int S, float* __restrict__ Cext,
                                          int m0, int n0){
    __shared__ int As_s[128*32];
    __shared__ int Bs_s[64*32];
    const int KI4 = HDIM/16;
    int tid = threadIdx.x;
    const int4* A4 = (const int4*)(g_aq[slot]);
    const int4* B4 = (const int4*)sgn_ptr(slot);

    int warp = tid>>5, lane = tid&31;
    int wm = warp&3, wn = warp>>2;
    int q = lane>>2, t = lane&3;

    int acc[2][4][4];
    #pragma unroll
    for (int mi=0;mi<2;mi++)
        #pragma unroll
        for (int ni=0;ni<4;ni++)
            #pragma unroll
            for (int e=0;e<4;e++) acc[mi][ni][e]=0;

    for (int k0=0; k0<HDIM; k0+=128){
        int kb = k0>>4;
        #pragma unroll
        for (int i=0;i<4;i++){
            int idx = tid + i*256;
            int r = idx>>3, b = idx&7;
            int4 val = A4[(size_t)(m0+r)*KI4 + kb + b];
            ((int4*)As_s)[r*8 + (b ^ (r&7))] = val;
        }
        #pragma unroll
        for (int i=0;i<2;i++){
            int idx = tid + i*256;
            int r = idx>>3, b = idx&7;
            int4 val = B4[(size_t)(n0+r)*KI4 + kb + b];
            ((int4*)Bs_s)[r*8 + (b ^ (r&7))] = val;
        }
        __syncthreads();
        #pragma unroll
        for (int s=0;s<4;s++){
            int a[2][4], bf[4][2];
            #pragma unroll
            for (int mi=0;mi<2;mi++){
                int r0 = wm*32 + mi*16 + q;
                int r1 = r0 + 8;
                a[mi][0] = As_s[r0*32 + ((2*s+0)^(r0&7))*4 + t];
                a[mi][1] = As_s[r1*32 + ((2*s+0)^(r1&7))*4 + t];
                a[mi][2] = As_s[r0*32 + ((2*s+1)^(r0&7))*4 + t];
                a[mi][3] = As_s[r1*32 + ((2*s+1)^(r1&7))*4 + t];
            }
            #pragma unroll
            for (int ni=0;ni<4;ni++){
                int rn = wn*32 + ni*8 + q;
                bf[ni][0] = Bs_s[rn*32 + ((2*s+0)^(rn&7))*4 + t];
                bf[ni][1] = Bs_s[rn*32 + ((2*s+1)^(rn&7))*4 + t];
            }
            #pragma unroll
            for (int mi=0;mi<2;mi++)
                #pragma unroll
                for (int ni=0;ni<4;ni++)
                    mma_s8(acc[mi][ni], a[mi], bf[ni]);
        }
        __syncthreads();
    }

    float ws = g_wscale[slot];
    float* Cq = (slot==0)? g_qb : (slot==1)? g_kb : g_vb;
    int NH = N>>7;
    #pragma unroll
    for (int mi=0;mi<2;mi++){
        #pragma unroll
        for (int h=0;h<2;h++){
            int m = m0 + wm*32 + mi*16 + q + 8*h;
            float fsc = g_as[slot][m]*ws;
            int b_ = m/S, sdx = m - b_*S;
            #pragma unroll
            for (int ni=0;ni<4;ni++){
                #pragma unroll
                for (int e=0;e<2;e++){
                    int n = n0 + wn*32 + ni*8 + t*2 + e;
                    float val = (float)acc[mi][ni][2*h+e]*fsc;
                    if (slot==3){
                        Cext[(size_t)m*N + n] = val;
                    } else {
                        int hh = n>>7, d = n&127;
                        Cq[(((size_t)(b_*NH+hh))*S + sdx)*HD + d] = val;
                    }
                }
            }
        }
    }
}

__global__ void __launch_bounds__(256) imma_qkv_kernel(int S){
    int slot = blockIdx.z;
    int N = (slot==0)? HDIM : KVH*HD;
    if (slot>0 && (int)blockIdx.x >= N/64) return;
    gemm_body(slot, N, S, nullptr, blockIdx.y*128, blockIdx.x*64);
}

__global__ void __launch_bounds__(256) imma_o_kernel(int S, float* __restrict__ Cext){
    gemm_body(3, HDIM, S, Cext, blockIdx.y*128, blockIdx.x*64);
}

// ---------------- RoPE (q and k fused, in-place) ----------------
__global__ void rope_all_kernel(int S, long tq, long total){
    long idx = blockIdx.x*(long)blockDim.x + threadIdx.x;
    if (idx>=total) return;
    float* buf; long lidx;
    if (idx < tq){ buf = g_qb; lidx = idx; }
    else         { buf = g_kb; lidx = idx - tq; }
    int i = (int)(lidx & 63);
    long row = lidx >> 6;
    int s = (int)(row % S);
    size_t base = (size_t)row*HD;
    float inv = powf(10000.f, -((float)i)*(1.f/64.f));
    float fr = (float)s * inv;
    float sn, cs; sincosf(fr,&sn,&cs);
    float x1 = buf[base+i], x2 = buf[base+i+64];
    buf[base+i]    = x1*cs - x2*sn;
    buf[base+i+64] = x2*cs + x1*sn;
}

// ---------------- flash attention (R7 shape; PV packed over kk via V^T) ----------------
// grid: (S/64, B*HEADS), 256 threads, occ 2.
// smem: Qs[64][130], KV buffer (K rows pitch 130 / V^T 128x66), Ss[64][66]
#define QP 130
#define VP 66
#define KVWORDS 8448   // max(64*130, 128*66)
__global__ void __launch_bounds__(256,2) flash_kernel(const float* __restrict__ mask, int S){
    extern __shared__ float sh[];
    float* Qs = sh;                   // 64*130 = 8320
    float* Ks = Qs + 64*QP;           // 8448 (K row-major, then V^T)
    float* Ss = Ks + KVWORDS;         // 64*66 = 4224
    int tid = threadIdx.x;
    int tq = blockIdx.x, bh = blockIdx.y;
    int b = bh/HEADS, h = bh%HEADS, hk = h/GROUPS;
    int sq0 = tq*64;
    const float* Qg = g_qb + (((size_t)bh)*S + sq0)*HD;
    const float* Kg = g_kb + ((size_t)(b*KVH+hk)*S)*HD;
    const float* Vg = g_vb + ((size_t)(b*KVH+hk)*S)*HD;

    for (int e=tid; e<64*64; e+=256){
        int r = e>>6, c = e&63;
        *(u64*)&Qs[r*QP + 2*c] = *(const u64*)&Qg[r*HD + 2*c];
    }

    int g = tid>>4, c0 = tid&15, r0 = g*4;
    float o4[4][8];
    #pragma unroll
    for (int i=0;i<4;i++)
        #pragma unroll
        for (int j=0;j<8;j++) o4[i][j]=0.f;
    float mreg[4], lreg[4];
    #pragma unroll
    for (int i=0;i<4;i++){ mreg[i] = __int_as_float(0xff800000); lreg[i]=0.f; }
    const float sc = 0.08838834764831845f;  // 1/sqrt(128)
    __syncthreads();

    int NT = S/64;
    for (int kt=0; kt<NT; kt++){
        const float* Kt = Kg + (size_t)kt*64*HD;
        for (int e=tid; e<64*64; e+=256){
            int r = e>>6, c = e&63;
            *(u64*)&Ks[r*QP + 2*c] = *(const u64*)&Kt[r*HD + 2*c];
        }
        __syncthreads();

        // --- QK^T with packed f32x2 over k (unchanged from R7) ---
        u64 acc2[4][4];
        #pragma unroll
        for (int i=0;i<4;i++)
            #pragma unroll
            for (int j=0;j<4;j++) acc2[i][j]=0ull;
        #pragma unroll 8
        for (int k=0;k<HD;k+=2){
            u64 a0 = ld2(&Qs[(r0+0)*QP+k]);
            u64 a1 = ld2(&Qs[(r0+1)*QP+k]);
            u64 a2 = ld2(&Qs[(r0+2)*QP+k]);
            u64 a3 = ld2(&Qs[(r0+3)*QP+k]);
            u64 b0 = ld2(&Ks[(c0+ 0)*QP+k]);
            u64 b1 = ld2(&Ks[(c0+16)*QP+k]);
            u64 b2 = ld2(&Ks[(c0+32)*QP+k]);
            u64 b3 = ld2(&Ks[(c0+48)*QP+k]);
            acc2[0][0]=fma2(a0,b0,acc2[0][0]); acc2[0][1]=fma2(a0,b1,acc2[0][1]);
            acc2[0][2]=fma2(a0,b2,acc2[0][2]); acc2[0][3]=fma2(a0,b3,acc2[0][3]);
            acc2[1][0]=fma2(a1,b0,acc2[1][0]); acc2[1][1]=fma2(a1,b1,acc2[1][1]);
            acc2[1][2]=fma2(a1,b2,acc2[1][2]); acc2[1][3]=fma2(a1,b3,acc2[1][3]);
            acc2[2][0]=fma2(a2,b0,acc2[2][0]); acc2[2][1]=fma2(a2,b1,acc2[2][1]);
            acc2[2][2]=fma2(a2,b2,acc2[2][2]); acc2[2][3]=fma2(a2,b3,acc2[2][3]);
            acc2[3][0]=fma2(a3,b0,acc2[3][0]); acc2[3][1]=fma2(a3,b1,acc2[3][1]);
            acc2[3][2]=fma2(a3,b2,acc2[3][2]); acc2[3][3]=fma2(a3,b3,acc2[3][3]);
        }

        float fac[4];
        #pragma unroll
        for (int i=0;i<4;i++){
            float s4[4];
            #pragma unroll
            for (int j=0;j<4;j++) s4[j] = lo2(acc2[i][j]) + hi2(acc2[i][j]);
            const float* mrow = mask + (size_t)(sq0+r0+i)*S + (size_t)kt*64;
            #pragma unroll
            for (int j=0;j<4;j++) s4[j] = s4[j]*sc + mrow[c0+16*j];
            float mx = fmaxf(fmaxf(s4[0],s4[1]),fmaxf(s4[2],s4[3]));
            mx = fmaxf(mx,__shfl_xor_sync(0xffffffffu,mx,1,16));
            mx = fmaxf(mx,__shfl_xor_sync(0xffffffffu,mx,2,16));
            mx = fmaxf(mx,__shfl_xor_sync(0xffffffffu,mx,4,16));
            mx = fmaxf(mx,__shfl_xor_sync(0xffffffffu,mx,8,16));
            float mn = fmaxf(mreg[i], mx);
            float su=0.f;
            #pragma unroll
            for (int j=0;j<4;j++){ float p = __expf(s4[j]-mn); s4[j]=p; su+=p; }
            su += __shfl_xor_sync(0xffffffffu,su,1,16);
            su += __shfl_xor_sync(0xffffffffu,su,2,16);
            su += __shfl_xor_sync(0xffffffffu,su,4,16);
            su += __shfl_xor_sync(0xffffffffu,su,8,16);
            float f = __expf(mreg[i]-mn);
            lreg[i] = lreg[i]*f + su;
            mreg[i] = mn;
            fac[i]  = f;
            #pragma unroll
            for (int j=0;j<4;j++) Ss[(r0+i)*VP + c0+16*j] = s4[j];
        }
        __syncthreads();

        // V fill TRANSPOSED: Vt[d][kk] (pitch 66). Coalesced LDG, 2-way STS.
        const float* Vt = Vg + (size_t)kt*64*HD;
        for (int e=tid; e<64*HD; e+=256){
            int kk = e>>7, d = e&127;
            Ks[d*VP + kk] = Vt[e];
        }
        // fold o*fac into pacc initial values (keeps reg peak low: o4 dead in loop)
        u64 pacc[4][8];
        #pragma unroll
        for (int i=0;i<4;i++){
            float f = fac[i];
            #pragma unroll
            for (int j=0;j<8;j++) pacc[i][j] = pack2f(o4[i][j]*f, 0.f);
        }
        __syncthreads();

        // --- P @ V: f32x2 packed over kk, zero pack instructions ---
        #pragma unroll 4
        for (int k2=0;k2<32;k2++){
            u64 pp0 = ld2(&Ss[(r0+0)*VP + 2*k2]);
            u64 pp1 = ld2(&Ss[(r0+1)*VP + 2*k2]);
            u64 pp2 = ld2(&Ss[(r0+2)*VP + 2*k2]);
            u64 pp3 = ld2(&Ss[(r0+3)*VP + 2*k2]);
            #pragma unroll
            for (int j=0;j<8;j++){
                u64 vv = ld2(&Ks[(c0+16*j)*VP + 2*k2]);
                pacc[0][j] = fma2(pp0, vv, pacc[0][j]);
                pacc[1][j] = fma2(pp1, vv, pacc[1][j]);
                pacc[2][j] = fma2(pp2, vv, pacc[2][j]);
                pacc[3][j] = fma2(pp3, vv, pacc[3][j]);
            }
        }
        #pragma unroll
        for (int i=0;i<4;i++)
            #pragma unroll
            for (int j=0;j<8;j++)
                o4[i][j] = lo2(pacc[i][j]) + hi2(pacc[i][j]);
        __syncthreads();
    }

    #pragma unroll
    for (int i=0;i<4;i++){
        float inv = 1.f/lreg[i];
        size_t rowbase = ((size_t)b*S + (size_t)(sq0+r0+i))*HDIM + (size_t)h*HD;
        #pragma unroll
        for (int j=0;j<8;j++)
            g_ao[rowbase + c0+16*j] = o4[i][j]*inv;
    }
}

// ---------------- launch ----------------
extern "C" void kernel_launch(void* const* d_in, const int* in_sizes, int n_in,
                              void* d_out, int out_size){
    const float* hidden = (const float*)d_in[0];
    const float* mask   = (const float*)d_in[1];
    const float* wq     = (const float*)d_in[2];
    const float* wk     = (const float*)d_in[3];
    const float* wv     = (const float*)d_in[4];
    const float* wo     = (const float*)d_in[5];
    const float* nq     = (const float*)d_in[6];
    const float* nk     = (const float*)d_in[7];
    const float* nv     = (const float*)d_in[8];
    const float* no_    = (const float*)d_in[9];
    float* out = (float*)d_out;

    int S = MAXS;
    {
        long ms = in_sizes[1];
        int s = (int)(sqrt((double)ms)+0.5);
        if ((long)s*s == ms) S = s;
    }
    int M = in_sizes[0]/HDIM;   // B*S rows
    int B = M/S;

    wstats_all_kernel<<<dim3(STATS_BLOCKS,4),256>>>(wq,wk,wv,wo);          // 1
    wsign_all_kernel<<<dim3(1024,4),256>>>(wq,wk,wv,wo);                    // 2
    act_quant3_kernel<<<M,256>>>(hidden, nq, nk, nv);                       // 3
    imma_qkv_kernel<<<dim3(HDIM/64, M/128, 3),256>>>(S);                    // 4

    long tq = (long)B*HEADS*S*64;
    long tk = (long)B*KVH*S*64;
    rope_all_kernel<<<(unsigned)((tq+tk+255)/256),256>>>(S, tq, tq+tk);     // 5

    const int FLASH_SMEM = (64*QP + KVWORDS + 64*VP)*4;  // 83968 bytes
    cudaFuncSetAttribute(flash_kernel, cudaFuncAttributeMaxDynamicSharedMemorySize, FLASH_SMEM);
    flash_kernel<<<dim3(S/64, B*HEADS),256,FLASH_SMEM>>>(mask, S);          // 6

    act_quant_kernel<<<M,256>>>(no_, 3);                                    // 7
    imma_o_kernel<<<dim3(HDIM/64, M/128),256>>>(S, out);                    // 8
}

// round 11
// speedup vs baseline: 1.1768x; 1.0707x over previous
#include <cuda_runtime.h>
#include <math.h>

typedef unsigned int u32;
typedef unsigned long long u64;

#define HEADS 16
#define KVH 8
#define HD 128
#define HDIM 2048
#define GROUPS (HEADS/KVH)
#define MAXB 2
#define MAXS 2048
#define MAXM (MAXB*MAXS)

#define NW_BIG   ((long)HDIM*HDIM)
#define NW_SMALL ((long)KVH*HD*HDIM)
#define STATS_BLOCKS 512

// ---------------- device scratch (no allocations allowed) ----------------
__device__ float g_ps[4][STATS_BLOCKS];
__device__ float g_pa[4][STATS_BLOCKS];
__device__ float g_wscale[4];

__device__ __align__(16) signed char g_sgn0[HDIM*HDIM];
__device__ __align__(16) signed char g_sgn1[KVH*HD*HDIM];
__device__ __align__(16) signed char g_sgn2[KVH*HD*HDIM];
__device__ __align__(16) signed char g_sgn3[HDIM*HDIM];
__device__ __align__(16) signed char g_aq[4][(size_t)MAXM*HDIM];
__device__ float g_as[4][MAXM];
__device__ float g_qb[(size_t)MAXB*HEADS*MAXS*HD];
__device__ float g_kb[(size_t)MAXB*KVH*MAXS*HD];
__device__ float g_vb[(size_t)MAXB*KVH*MAXS*HD];
__device__ float g_ao[(size_t)MAXM*HDIM];

__device__ __forceinline__ signed char* sgn_ptr(int s){
    return (s==0)?g_sgn0:(s==1)?g_sgn1:(s==2)?g_sgn2:g_sgn3;
}

// ---------------- packed fp32x2 helpers ----------------
__device__ __forceinline__ u64 ld2(const float* p){
    return *reinterpret_cast<const u64*>(p);
}
__device__ __forceinline__ u64 fma2(u64 a, u64 b, u64 c){
    u64 d;
    asm("fma.rn.f32x2 %0, %1, %2, %3;" : "=l"(d) : "l"(a), "l"(b), "l"(c));
    return d;
}
__device__ __forceinline__ u64 pack2f(float lo, float hi){
    u64 r;
    asm("mov.b64 %0, {%1, %2};" : "=l"(r) : "f"(lo), "f"(hi));
    return r;
}
__device__ __forceinline__ float lo2(u64 v){
    float a; asm("{ .reg .b32 hi; mov.b64 {%0, hi}, %1; }" : "=f"(a) : "l"(v)); return a;
}
__device__ __forceinline__ float hi2(u64 v){
    float a; asm("{ .reg .b32 lo; mov.b64 {lo, %0}, %1; }" : "=f"(a) : "l"(v)); return a;
}

// ---------------- cp.async helpers ----------------
__device__ __forceinline__ u32 smem_u32p(const void* p){
    u32 a;
    asm("{ .reg .u64 t; cvta.to.shared.u64 t, %1; cvt.u32.u64 %0, t; }" : "=r"(a) : "l"(p));
    return a;
}
__device__ __forceinline__ void cpa16(u32 dst, const void* src){
    asm volatile("cp.async.cg.shared.global [%0], [%1], 16;" :: "r"(dst), "l"(src));
}
__device__ __forceinline__ void cpa_commit(){
    asm volatile("cp.async.commit_group;" ::: "memory");
}
__device__ __forceinline__ void cpa_wait0(){
    asm volatile("cp.async.wait_group 0;" ::: "memory");
}

// ---------------- weight statistics ----------------
__global__ void wstats_all_kernel(const float* __restrict__ wq, const float* __restrict__ wk,
                                  const float* __restrict__ wv, const float* __restrict__ wo){
    int slot = blockIdx.y;
    const float* W = (slot==0)?wq:(slot==1)?wk:(slot==2)?wv:wo;
    long n = (slot==0 || slot==3)? NW_BIG : NW_SMALL;
    float s=0.f, a=0.f;
    long stride = (long)gridDim.x*blockDim.x;
    for (long i = blockIdx.x*(long)blockDim.x + threadIdx.x; i<n; i+=stride){
        float w = W[i]; s += w; a += fabsf(w);
    }
    __shared__ float rs[256], ra[256];
    rs[threadIdx.x]=s; ra[threadIdx.x]=a; __syncthreads();
    for (int o=128;o>0;o>>=1){
        if ((int)threadIdx.x<o){ rs[threadIdx.x]+=rs[threadIdx.x+o]; ra[threadIdx.x]+=ra[threadIdx.x+o]; }
        __syncthreads();
    }
    if (threadIdx.x==0){
        g_ps[slot][blockIdx.x]=rs[0];
        g_pa[slot][blockIdx.x]=ra[0];
    }
}

__global__ void wsign_all_kernel(const float* __restrict__ wq, const float* __restrict__ wk,
                                 const float* __restrict__ wv, const float* __restrict__ wo){
    int slot = blockIdx.y;
    const float* W = (slot==0)?wq:(slot==1)?wk:(slot==2)?wv:wo;
    long n = (slot==0 || slot==3)? NW_BIG : NW_SMALL;
    __shared__ float rs[256], ra[256];
    {
        float s = g_ps[slot][threadIdx.x] + g_ps[slot][threadIdx.x+256];
        float a = g_pa[slot][threadIdx.x] + g_pa[slot][threadIdx.x+256];
        rs[threadIdx.x]=s; ra[threadIdx.x]=a; __syncthreads();
        for (int o=128;o>0;o>>=1){
            if ((int)threadIdx.x<o){ rs[threadIdx.x]+=rs[threadIdx.x+o]; ra[threadIdx.x]+=ra[threadIdx.x+o]; }
            __syncthreads();
        }
    }
    float e  = rs[0]/(float)n;
    float sc = fmaxf(ra[0]/(float)n, 1e-8f);
    if (blockIdx.x==0 && threadIdx.x==0) g_wscale[slot]=sc;
    signed char* S8 = sgn_ptr(slot);
    long stride = (long)gridDim.x*blockDim.x;
    for (long i = blockIdx.x*(long)blockDim.x + threadIdx.x; i<n; i+=stride){
        float d = W[i]-e;
        S8[i] = (d>0.f)?(signed char)1:((d<0.f)?(signed char)-1:(signed char)0);
    }
}

// ---------------- rmsnorm + activation quant ----------------
__global__ void act_quant3_kernel(const float* __restrict__ X,
                                  const float* __restrict__ nq,
                                  const float* __restrict__ nk,
                                  const float* __restrict__ nv){
    int m = blockIdx.x, tid = threadIdx.x;
    const float* x = X + (size_t)m*HDIM;
    float v[8]; float ss=0.f;
    #pragma unroll
    for (int i=0;i<8;i++){
        float f = x[tid + i*256];
        f = fminf(fmaxf(f,-100.f),100.f);
        v[i]=f; ss += f*f;
    }
    __shared__ float red[256];
    red[tid]=ss; __syncthreads();
    for (int o=128;o>0;o>>=1){ if (tid<o) red[tid]+=red[tid+o]; __syncthreads(); }
    float var = red[0]*(1.f/(float)HDIM);
    var = fmaxf(var, 1e-5f);
    float rs = 1.f/sqrtf(var + 1e-5f);
    __syncthreads();
    #pragma unroll
    for (int i=0;i<8;i++){
        float b = v[i]*rs;
        v[i] = fminf(fmaxf(b,-10.f),10.f);
    }
    const float* nws[3] = {nq, nk, nv};
    #pragma unroll 1
    for (int slot=0; slot<3; slot++){
        const float* nw = nws[slot];
        float w[8]; float mx=0.f;
        #pragma unroll
        for (int i=0;i<8;i++){
            float t = v[i]*nw[tid+i*256];
            t = fminf(fmaxf(t,-50.f),50.f);
            w[i]=t; mx = fmaxf(mx, fabsf(t));
        }
        red[tid]=mx; __syncthreads();
        for (int o=128;o>0;o>>=1){ if (tid<o) red[tid]=fmaxf(red[tid],red[tid+o]); __syncthreads(); }
        float maxv = fmaxf(red[0], 1e-4f);
        __syncthreads();
        float scale = 127.f/maxv;
        signed char* out8 = g_aq[slot] + (size_t)m*HDIM;
        #pragma unroll
        for (int i=0;i<8;i++){
            int q = __float2int_rn(w[i]*scale);
            q = max(-128, min(127, q));
            out8[tid+i*256] = (signed char)q;
        }
        if (tid==0) g_as[slot][m] = maxv*(1.f/127.f);
    }
}

__global__ void act_quant_kernel(const float* __restrict__ nw, int slot){
    const float* X = g_ao;
    int m = blockIdx.x, tid = threadIdx.x;
    const float* x = X + (size_t)m*HDIM;
    float v[8]; float ss=0.f;
    #pragma unroll
    for (int i=0;i<8;i++){
        float f = x[tid + i*256];
        f = fminf(fmaxf(f,-100.f),100.f);
        v[i]=f; ss += f*f;
    }
    __shared__ float red[256];
    red[tid]=ss; __syncthreads();
    for (int o=128;o>0;o>>=1){ if (tid<o) red[tid]+=red[tid+o]; __syncthreads(); }
    float var = red[0]*(1.f/(float)HDIM);
    var = fmaxf(var, 1e-5f);
    float rs = 1.f/sqrtf(var + 1e-5f);
    __syncthreads();
    float mx=0.f;
    #pragma unroll
    for (int i=0;i<8;i++){
        float b = v[i]*rs;
        b = fminf(fmaxf(b,-10.f),10.f);
        float w = b*nw[tid+i*256];
        w = fminf(fmaxf(w,-50.f),50.f);
        v[i]=w; mx = fmaxf(mx, fabsf(w));
    }
    red[tid]=mx; __syncthreads();
    for (int o=128;o>0;o>>=1){ if (tid<o) red[tid]=fmaxf(red[tid],red[tid+o]); __syncthreads(); }
    float maxv = fmaxf(red[0], 1e-4f);
    float scale = 127.f/maxv;
    signed char* out8 = g_aq[slot] + (size_t)m*HDIM;
    #pragma unroll
    for (int i=0;i<8;i++){
        int q = __float2int_rn(v[i]*scale);
        q = max(-128, min(127, q));
        out8[tid+i*256] = (signed char)q;
    }
    if (tid==0) g_as[slot][m] = maxv*(1.f/127.f);
}

// ---------------- int8 x ternary GEMM via mma.sync, cp.async double-buffered ----------------
__device__ __forceinline__ void mma_s8(int* c, const int* a, const int* b){
    asm volatile(
        "mma.sync.aligned.m16n8k32.row.col.s32.s8.s8.s32 "
        "{%0,%1,%2,%3}, {%4,%5,%6,%7}, {%8,%9}, {%0,%1,%2,%3};\n"
        : "+r"(c[0]), "+r"(c[1]), "+r"(c[2]), "+r"(c[3])
        : "r"(a[0]), "r"(a[1]), "r"(a[2]), "r"(a[3]), "r"(b[0]), "r"(b[1]));
}

#define BUF_I4 1536   // per-buffer int4 count: A=1024 (128x8), B=512 (64x8)

__device__ __forceinline__ void gemm_body(int slot, int N, int S, float* __restrict__ Cext,
                                          int m0, int n0){
    __shared__ int4 AB[2][BUF_I4];   // 48 KB total
    const int KI4 = HDIM/16;         // 128 int4 per row
    int tid = threadIdx.x;
    const int4* A4 = (const int4*)(g_aq[slot]);
    const int4* B4 = (const int4*)sgn_ptr(slot);
    u32 sbase = smem_u32p(&AB[0][0]);

    int warp = tid>>5, lane = tid&31;
    int wm = warp&3, wn = warp>>2;
    int q = lane>>2, t = lane&3;

    int acc[2][4][4];
    #pragma unroll
    for (int mi=0;mi<2;mi++)
        #pragma unroll
        for (int ni=0;ni<4;ni++)
            #pragma unroll
            for (int e=0;e<4;e++) acc[mi][ni][e]=0;

    // issue chunk 0
    {
        int kb = 0;
        u32 bb = sbase;
        #pragma unroll
        for (int i=0;i<4;i++){
            int idx = tid + i*256; int r = idx>>3, b = idx&7;
            cpa16(bb + (u32)(r*8 + (b^(r&7)))*16u, &A4[(size_t)(m0+r)*KI4 + kb + b]);
        }
        #pragma unroll
        for (int i=0;i<2;i++){
            int idx = tid + i*256; int r = idx>>3, b = idx&7;
            cpa16(bb + (u32)(1024 + r*8 + (b^(r&7)))*16u, &B4[(size_t)(n0+r)*KI4 + kb + b]);
        }
        cpa_commit();
    }

    for (int c=0; c<16; c++){
        cpa_wait0();
        __syncthreads();
        if (c+1 < 16){
            int kb = (c+1)*8;
            u32 bb = sbase + (u32)((c+1)&1)*BUF_I4*16u;
            #pragma unroll
            for (int i=0;i<4;i++){
                int idx = tid + i*256; int r = idx>>3, b = idx&7;
                cpa16(bb + (u32)(r*8 + (b^(r&7)))*16u, &A4[(size_t)(m0+r)*KI4 + kb + b]);
            }
            #pragma unroll
            for (int i=0;i<2;i++){
                int idx = tid + i*256; int r = idx>>3, b = idx&7;
                cpa16(bb + (u32)(1024 + r*8 + (b^(r&7)))*16u, &B4[(size_t)(n0+r)*KI4 + kb + b]);
            }
            cpa_commit();
        }
        const int* As_s = (const int*)&AB[c&1][0];
        const int* Bs_s = (const int*)&AB[c&1][1024];
        #pragma unroll
        for (int s=0;s<4;s++){
            int a[2][4], bf[4][2];
            #pragma unroll
            for (int mi=0;mi<2;mi++){
                int r0 = wm*32 + mi*16 + q;
                int r1 = r0 + 8;
                a[mi][0] = As_s[r0*32 + ((2*s+0)^(r0&7))*4 + t];
                a[mi][1] = As_s[r1*32 + ((2*s+0)^(r1&7))*4 + t];
                a[mi][2] = As_s[r0*32 + ((2*s+1)^(r0&7))*4 + t];
                a[mi][3] = As_s[r1*32 + ((2*s+1)^(r1&7))*4 + t];
            }
            #pragma unroll
            for (int ni=0;ni<4;ni++){
                int rn = wn*32 + ni*8 + q;
                bf[ni][0] = Bs_s[rn*32 + ((2*s+0)^(rn&7))*4 + t];
                bf[ni][1] = Bs_s[rn*32 + ((2*s+1)^(rn&7))*4 + t];
            }
            #pragma unroll
            for (int mi=0;mi<2;mi++)
                #pragma unroll
                for (int ni=0;ni<4;ni++)
                    mma_s8(acc[mi][ni], a[mi], bf[ni]);
        }
    }

    float ws = g_wscale[slot];
    float* Cq = (slot==0)? g_qb : (slot==1)? g_kb : g_vb;
    int NH = N>>7;
    #pragma unroll
    for (int mi=0;mi<2;mi++){
        #pragma unroll
        for (int h=0;h<2;h++){
            int m = m0 + wm*32 + mi*16 + q + 8*h;
            float fsc = g_as[slot][m]*ws;
            int b_ = m/S, sdx = m - b_*S;
            #pragma unroll
            for (int ni=0;ni<4;ni++){
                #pragma unroll
                for (int e=0;e<2;e++){
                    int n = n0 + wn*32 + ni*8 + t*2 + e;
                    float val = (float)acc[mi][ni][2*h+e]*fsc;
                    if (slot==3){
                        Cext[(size_t)m*N + n] = val;
                    } else {
                        int hh = n>>7, d = n&127;
                        Cq[(((size_t)(b_*NH+hh))*S + sdx)*HD + d] = val;
                    }
                }
            }
        }
    }
}

__global__ void __launch_bounds__(256) imma_qkv_kernel(int S){
    int slot = blockIdx.z;
    int N = (slot==0)? HDIM : KVH*HD;
    if (slot>0 && (int)blockIdx.x >= N/64) return;
    gemm_body(slot, N, S, nullptr, blockIdx.y*128, blockIdx.x*64);
}

__global__ void __launch_bounds__(256) imma_o_kernel(int S, float* __restrict__ Cext){
    gemm_body(3, HDIM, S, Cext, blockIdx.y*128, blockIdx.x*64);
}

// ---------------- RoPE (q and k fused, in-place) ----------------
__global__ void rope_all_kernel(int S, long tq, long total){
    long idx = blockIdx.x*(long)blockDim.x + threadIdx.x;
    if (idx>=total) return;
    float* buf; long lidx;
    if (idx < tq){ buf = g_qb; lidx = idx; }
    else         { buf = g_kb; lidx = idx - tq; }
    int i = (int)(lidx & 63);
    long row = lidx >> 6;
    int s = (int)(row % S);
    size_t base = (size_t)row*HD;
    float inv = powf(10000.f, -((float)i)*(1.f/64.f));
    float fr = (float)s * inv;
    float sn, cs; sincosf(fr,&sn,&cs);
    float x1 = buf[base+i], x2 = buf[base+i+64];
    buf[base+i]    = x1*cs - x2*sn;
    buf[base+i+64] = x2*cs + x1*sn;
}

// ---------------- flash attention (R10 shape + reg-prefetch of V and next-K) ----------------
// grid: (S/64, B*HEADS), 256 threads, occ 2.
// smem: Qs[64][130], KV buffer (K rows pitch 130 / V^T 128x66), Ss[64][66]
#define QP 130
#define VP 66
#define KVWORDS 8448   // max(64*130, 128*66)
__global__ void __launch_bounds__(256,2) flash_kernel(const float* __restrict__ mask, int S){
    extern __shared__ float sh[];
    float* Qs = sh;                   // 64*130 = 8320
    float* Ks = Qs + 64*QP;           // 8448 (K row-major, then V^T)
    float* Ss = Ks + KVWORDS;         // 64*66 = 4224
    int tid = threadIdx.x;
    int tq = blockIdx.x, bh = blockIdx.y;
    int b = bh/HEADS, h = bh%HEADS, hk = h/GROUPS;
    int sq0 = tq*64;
    const float* Qg = g_qb + (((size_t)bh)*S + sq0)*HD;
    const float* Kg = g_kb + ((size_t)(b*KVH+hk)*S)*HD;
    const float* Vg = g_vb + ((size_t)(b*KVH+hk)*S)*HD;

    for (int e=tid; e<64*64; e+=256){
        int r = e>>6, c = e&63;
        *(u64*)&Qs[r*QP + 2*c] = *(const u64*)&Qg[r*HD + 2*c];
    }
    // initial K fill (tile 0)
    #pragma unroll
    for (int i=0;i<16;i++){
        int e = tid + i*256;
        *(u64*)&Ks[(e>>6)*QP + (e&63)*2] = *(const u64*)&Kg[(e>>6)*HD + (e&63)*2];
    }

    int g = tid>>4, c0 = tid&15, r0 = g*4;
    float o4[4][8];
    #pragma unroll
    for (int i=0;i<4;i++)
        #pragma unroll
        for (int j=0;j<8;j++) o4[i][j]=0.f;
    float mreg[4], lreg[4];
    #pragma unroll
    for (int i=0;i<4;i++){ mreg[i] = __int_as_float(0xff800000); lreg[i]=0.f; }
    const float sc = 0.08838834764831845f;  // 1/sqrt(128)

    int NT = S/64;
    for (int kt=0; kt<NT; kt++){
        __syncthreads();   // K (and Q on first iter) ready

        // --- QK^T with packed f32x2 over k ---
        u64 acc2[4][4];
        #pragma unroll
        for (int i=0;i<4;i++)
            #pragma unroll
            for (int j=0;j<4;j++) acc2[i][j]=0ull;
        #pragma unroll 8
        for (int k=0;k<HD;k+=2){
            u64 a0 = ld2(&Qs[(r0+0)*QP+k]);
            u64 a1 = ld2(&Qs[(r0+1)*QP+k]);
            u64 a2 = ld2(&Qs[(r0+2)*QP+k]);
            u64 a3 = ld2(&Qs[(r0+3)*QP+k]);
            u64 b0 = ld2(&Ks[(c0+ 0)*QP+k]);
            u64 b1 = ld2(&Ks[(c0+16)*QP+k]);
            u64 b2 = ld2(&Ks[(c0+32)*QP+k]);
            u64 b3 = ld2(&Ks[(c0+48)*QP+k]);
            acc2[0][0]=fma2(a0,b0,acc2[0][0]); acc2[0][1]=fma2(a0,b1,acc2[0][1]);
            acc2[0][2]=fma2(a0,b2,acc2[0][2]); acc2[0][3]=fma2(a0,b3,acc2[0][3]);
            acc2[1][0]=fma2(a1,b0,acc2[1][0]); acc2[1][1]=fma2(a1,b1,acc2[1][1]);
            acc2[1][2]=fma2(a1,b2,acc2[1][2]); acc2[1][3]=fma2(a1,b3,acc2[1][3]);
            acc2[2][0]=fma2(a2,b0,acc2[2][0]); acc2[2][1]=fma2(a2,b1,acc2[2][1]);
            acc2[2][2]=fma2(a2,b2,acc2[2][2]); acc2[2][3]=fma2(a2,b3,acc2[2][3]);
            acc2[3][0]=fma2(a3,b0,acc2[3][0]); acc2[3][1]=fma2(a3,b1,acc2[3][1]);
            acc2[3][2]=fma2(a3,b2,acc2[3][2]); acc2[3][3]=fma2(a3,b3,acc2[3][3]);
        }

        // --- V prefetch into registers (coalesced; covered by softmax) ---
        u64 vpre[16];
        {
            const float* Vt = Vg + (size_t)kt*64*HD;
            #pragma unroll
            for (int i=0;i<16;i++){
                int e  = tid + i*256;
                int dp = (e&15) | (((e>>5)&3)<<4);
                int kk = ((e>>4)&1) | ((e>>7)<<1);
                vpre[i] = *(const u64*)&Vt[kk*HD + 2*dp];
            }
        }

        // --- online softmax ---
        float fac[4];
        #pragma unroll
        for (int i=0;i<4;i++){
            float s4[4];
            #pragma unroll
            for (int j=0;j<4;j++) s4[j] = lo2(acc2[i][j]) + hi2(acc2[i][j]);
            const float* mrow = mask + (size_t)(sq0+r0+i)*S + (size_t)kt*64;
            #pragma unroll
            for (int j=0;j<4;j++) s4[j] = s4[j]*sc + mrow[c0+16*j];
            float mx = fmaxf(fmaxf(s4[0],s4[1]),fmaxf(s4[2],s4[3]));
            mx = fmaxf(mx,__shfl_xor_sync(0xffffffffu,mx,1,16));
            mx = fmaxf(mx,__shfl_xor_sync(0xffffffffu,mx,2,16));
            mx = fmaxf(mx,__shfl_xor_sync(0xffffffffu,mx,4,16));
            mx = fmaxf(mx,__shfl_xor_sync(0xffffffffu,mx,8,16));
            float mn = fmaxf(mreg[i], mx);
            float su=0.f;
            #pragma unroll
            for (int j=0;j<4;j++){ float p = __expf(s4[j]-mn); s4[j]=p; su+=p; }
            su += __shfl_xor_sync(0xffffffffu,su,1,16);
            su += __shfl_xor_sync(0xffffffffu,su,2,16);
            su += __shfl_xor_sync(0xffffffffu,su,4,16);
            su += __shfl_xor_sync(0xffffffffu,su,8,16);
            float f = __expf(mreg[i]-mn);
            lreg[i] = lreg[i]*f + su;
            mreg[i] = mn;
            fac[i]  = f;
            #pragma unroll
            for (int j=0;j<4;j++) Ss[(r0+i)*VP + c0+16*j] = s4[j];
        }
        __syncthreads();   // K reads done, P visible

        // --- store V^T from prefetched regs ---
        #pragma unroll
        for (int i=0;i<16;i++){
            int e  = tid + i*256;
            int dp = (e&15) | (((e>>5)&3)<<4);
            int kk = ((e>>4)&1) | ((e>>7)<<1);
            int d  = 2*dp;
            Ks[d*VP + kk]     = lo2(vpre[i]);
            Ks[(d+1)*VP + kk] = hi2(vpre[i]);
        }

        // --- prefetch half of next K tile (covered by PV) ---
        u64 kpre[8];
        const float* Kn = Kg + (size_t)(kt+1)*64*HD;
        if (kt+1 < NT){
            #pragma unroll
            for (int i=0;i<8;i++){
                int e = tid + i*256;
                kpre[i] = *(const u64*)&Kn[(e>>6)*HD + (e&63)*2];
            }
        }

        // fold o*fac into pacc initial values
        u64 pacc[4][8];
        #pragma unroll
        for (int i=0;i<4;i++){
            float f = fac[i];
            #pragma unroll
            for (int j=0;j<8;j++) pacc[i][j] = pack2f(o4[i][j]*f, 0.f);
        }
        __syncthreads();   // V^T ready

        // --- P @ V: f32x2 packed over kk ---
        #pragma unroll 4
        for (int k2=0;k2<32;k2++){
            u64 pp0 = ld2(&Ss[(r0+0)*VP + 2*k2]);
            u64 pp1 = ld2(&Ss[(r0+1)*VP + 2*k2]);
            u64 pp2 = ld2(&Ss[(r0+2)*VP + 2*k2]);
            u64 pp3 = ld2(&Ss[(r0+3)*VP + 2*k2]);
            #pragma unroll
            for (int j=0;j<8;j++){
                u64 vv = ld2(&Ks[(c0+16*j)*VP + 2*k2]);
                pacc[0][j] = fma2(pp0, vv, pacc[0][j]);
                pacc[1][j] = fma2(pp1, vv, pacc[1][j]);
                pacc[2][j] = fma2(pp2, vv, pacc[2][j]);
                pacc[3][j] = fma2(pp3, vv, pacc[3][j]);
            }
        }
        #pragma unroll
        for (int i=0;i<4;i++)
            #pragma unroll
            for (int j=0;j<8;j++)
                o4[i][j] = lo2(pacc[i][j]) + hi2(pacc[i][j]);
        __syncthreads();   // V^T reads done

        // --- fill next K tile (half from regs, half direct) ---
        if (kt+1 < NT){
            #pragma unroll
            for (int i=0;i<8;i++){
                int e = tid + i*256;
                *(u64*)&Ks[(e>>6)*QP + (e&63)*2] = kpre[i];
            }
            #pragma unroll
            for (int i=8;i<16;i++){
                int e = tid + i*256;
                *(u64*)&Ks[(e>>6)*QP + (e&63)*2] = *(const u64*)&Kn[(e>>6)*HD + (e&63)*2];
            }
        }
    }

    #pragma unroll
    for (int i=0;i<4;i++){
        float inv = 1.f/lreg[i];
        size_t rowbase = ((size_t)b*S + (size_t)(sq0+r0+i))*HDIM + (size_t)h*HD;
        #pragma unroll
        for (int j=0;j<8;j++)
            g_ao[rowbase + c0+16*j] = o4[i][j]*inv;
    }
}

// ---------------- launch ----------------
extern "C" void kernel_launch(void* const* d_in, const int* in_sizes, int n_in,
                              void* d_out, int out_size){
    const float* hidden = (const float*)d_in[0];
    const float* mask   = (const float*)d_in[1];
    const float* wq     = (const float*)d_in[2];
    const float* wk     = (const float*)d_in[3];
    const float* wv     = (const float*)d_in[4];
    const float* wo     = (const float*)d_in[5];
    const float* nq     = (const float*)d_in[6];
    const float* nk     = (const float*)d_in[7];
    const float* nv     = (const float*)d_in[8];
    const float* no_    = (const float*)d_in[9];
    float* out = (float*)d_out;

    int S = MAXS;
    {
        long ms = in_sizes[1];
        int s = (int)(sqrt((double)ms)+0.5);
        if ((long)s*s == ms) S = s;
    }
    int M = in_sizes[0]/HDIM;   // B*S rows
    int B = M/S;

    wstats_all_kernel<<<dim3(STATS_BLOCKS,4),256>>>(wq,wk,wv,wo);          // 1
    wsign_all_kernel<<<dim3(1024,4),256>>>(wq,wk,wv,wo);                    // 2
    act_quant3_kernel<<<M,256>>>(hidden, nq, nk, nv);                       // 3
    imma_qkv_kernel<<<dim3(HDIM/64, M/128, 3),256>>>(S);                    // 4

    long tq = (long)B*HEADS*S*64;
    long tk = (long)B*KVH*S*64;
    rope_all_kernel<<<(unsigned)((tq+tk+255)/256),256>>>(S, tq, tq+tk);     // 5

    const int FLASH_SMEM = (64*QP + KVWORDS + 64*VP)*4;  // 83968 bytes
    cudaFuncSetAttribute(flash_kernel, cudaFuncAttributeMaxDynamicSharedMemorySize, FLASH_SMEM);
    flash_kernel<<<dim3(S/64, B*HEADS),256,FLASH_SMEM>>>(mask, S);          // 6

    act_quant_kernel<<<M,256>>>(no_, 3);                                    // 7
    imma_o_kernel<<<dim3(HDIM/64, M/128),256>>>(S, out);                    // 8
}